// round 11
// baseline (speedup 1.0000x reference)
#include <cuda_runtime.h>
#include <cuda_fp16.h>
#include <cstdint>

// ---------------- static problem config ----------------
#define Bc 2
#define Tc 8
#define Hc 64
#define Wc 64
#define Cc 128
#define TSP 2
#define HSP 64
#define WSP 4
#define HD 32
#define NTOK 512
#define Lc (Tc*Hc*Wc)
#define SCALE_F 0.17677669529663687f
#define QSCALE (SCALE_F * 1.4426950408889634f)   // fold log2e: softmax via 2^S

// ---------------- smem layout (bytes) ----------------
// Vts: 32 rows x 520 halves (1040B rows, conflict-free PV frags: banks 4r+tg)
// Ks : 512 rows x 40 halves (80B rows, conflict-free QK frags: banks 20r+tg)
// Osm: 512 rows x 36 floats (144B rows, 16B-aligned f4 epilogue reads), ALIASES Ks
#define VTS_OFF  0
#define W_OFF    33280
#define B_OFF    36736
#define KS_OFF   36864
#define OSM_OFF  36864
#define SM_TOTAL 110592

static __device__ __forceinline__ void mma_f16(float* d, const uint32_t* a, const uint32_t* b) {
    asm volatile(
        "mma.sync.aligned.m16n8k16.row.col.f32.f16.f16.f32 "
        "{%0,%1,%2,%3}, {%4,%5,%6,%7}, {%8,%9}, {%0,%1,%2,%3};"
        : "+f"(d[0]), "+f"(d[1]), "+f"(d[2]), "+f"(d[3])
        : "r"(a[0]), "r"(a[1]), "r"(a[2]), "r"(a[3]), "r"(b[0]), "r"(b[1]));
}

// 2^x on the FMA pipe (input already in log2 domain): magic-round + deg-4 poly
static __device__ __forceinline__ float fast_exp2(float t) {
    float r = t + 12582912.0f;                 // round-to-nearest int in mantissa
    float f = t - (r - 12582912.0f);           // f in [-0.5, 0.5]
    float p = 0.00961804886f;
    p = fmaf(p, f, 0.0555036958f);
    p = fmaf(p, f, 0.240226344f);
    p = fmaf(p, f, 0.693147180f);
    p = fmaf(p, f, 1.0f);
    return __int_as_float(__float_as_int(p) + (__float_as_int(r) << 23));
}

static __device__ __forceinline__ uint32_t pack_h2(float a, float b) {
    __half2 h = __floats2half2_rn(a, b);
    return reinterpret_cast<uint32_t&>(h);
}

__global__ void __launch_bounds__(1024, 1)
lepe_attn_hmma(const float* __restrict__ qkv, const float* __restrict__ lepe_w,
               const float* __restrict__ lepe_b, float* __restrict__ out)
{
    extern __shared__ char smem[];
    __half* Ks  = (__half*)(smem + KS_OFF);    // [512][40]
    __half* Vts = (__half*)(smem + VTS_OFF);   // [32][520]
    float*  Osm = (float*)(smem + OSM_OFF);    // [512][36]  (aliases Ks)
    float*  Wsm = (float*)(smem + W_OFF);      // [27][32]
    float*  Bsm = (float*)(smem + B_OFF);      // [32]

    const int tid  = threadIdx.x;
    const int lane = tid & 31;
    const int warp = tid >> 5;
    const int r    = lane >> 2;
    const int tg   = lane & 3;

    const int wh = blockIdx.x;
    const int head = wh & 3;
    const int w  = wh >> 2;
    const int b  = w >> 6;
    const int tb = (w >> 4) & 3;
    const int wb = w & 15;
    const int cbase = head * HD;

    const float* qg = qkv + (size_t)b * Lc * Cc;
    const float* kg = qkv + (size_t)(Bc + b) * Lc * Cc;
    const float* vg = qkv + (size_t)(2 * Bc + b) * Lc * Cc;

    // ---- cooperative load: K -> fp16 rows, V -> fp16 transposed ----
    for (int idx = tid; idx < NTOK * 8; idx += 1024) {
        int tok = idx >> 3;
        int f   = idx & 7;
        int ts  = tok >> 8;
        int hs  = (tok >> 2) & 63;
        int ws  = tok & 3;
        int l   = ((tb * TSP + ts) * Hc + hs) * Wc + wb * WSP + ws;
        size_t off = (size_t)l * Cc + cbase + f * 4;
        float4 fk = *(const float4*)(kg + off);
        float4 fv = *(const float4*)(vg + off);
        uint2 kp;
        kp.x = pack_h2(fk.x, fk.y);
        kp.y = pack_h2(fk.z, fk.w);
        *(uint2*)(Ks + tok * 40 + f * 4) = kp;
        Vts[(f * 4 + 0) * 520 + tok] = __float2half_rn(fv.x);
        Vts[(f * 4 + 1) * 520 + tok] = __float2half_rn(fv.y);
        Vts[(f * 4 + 2) * 520 + tok] = __float2half_rn(fv.z);
        Vts[(f * 4 + 3) * 520 + tok] = __float2half_rn(fv.w);
    }
    if (tid < 27 * HD) {
        int d = tid & 31, j = tid >> 5;
        Wsm[j * HD + d] = lepe_w[(size_t)(cbase + d) * 27 + j];
    }
    if (tid >= 992) Bsm[tid - 992] = lepe_b[cbase + tid - 992];

    // ---- per-warp Q fragments straight from gmem (16 rows, pre-scaled) ----
    const int lr = warp << 4;                 // this warp's 16 query rows
    uint32_t qa[2][4];
    {
        int n0 = lr + r, n1 = n0 + 8;
        int l0 = ((tb * TSP + (n0 >> 8)) * Hc + ((n0 >> 2) & 63)) * Wc + wb * WSP + (n0 & 3);
        int l1 = ((tb * TSP + (n1 >> 8)) * Hc + ((n1 >> 2) & 63)) * Wc + wb * WSP + (n1 & 3);
        const float* q0p = qg + (size_t)l0 * Cc + cbase;
        const float* q1p = qg + (size_t)l1 * Cc + cbase;
        #pragma unroll
        for (int ks = 0; ks < 2; ks++) {
            float2 x;
            x = *(const float2*)(q0p + 16 * ks + 2 * tg);
            qa[ks][0] = pack_h2(x.x * QSCALE, x.y * QSCALE);
            x = *(const float2*)(q1p + 16 * ks + 2 * tg);
            qa[ks][1] = pack_h2(x.x * QSCALE, x.y * QSCALE);
            x = *(const float2*)(q0p + 16 * ks + 2 * tg + 8);
            qa[ks][2] = pack_h2(x.x * QSCALE, x.y * QSCALE);
            x = *(const float2*)(q1p + 16 * ks + 2 * tg + 8);
            qa[ks][3] = pack_h2(x.x * QSCALE, x.y * QSCALE);
        }
    }
    __syncthreads();

    // ---- flash over 16 chunks of 32 keys (16 rows per warp) ----
    float o[4][4];
    #pragma unroll
    for (int nd = 0; nd < 4; nd++)
        #pragma unroll
        for (int k = 0; k < 4; k++) o[nd][k] = 0.f;
    float lsum0 = 0.f, lsum1 = 0.f;

    #pragma unroll 1
    for (int chunk = 0; chunk < 16; chunk++) {
        const int kb = chunk * 32;

        float s[4][4];
        #pragma unroll
        for (int nt = 0; nt < 4; nt++)
            #pragma unroll
            for (int k = 0; k < 4; k++) s[nt][k] = 0.f;

        #pragma unroll
        for (int nt = 0; nt < 4; nt++) {
            const uint32_t* krow = (const uint32_t*)(Ks + (kb + nt * 8 + r) * 40);
            #pragma unroll
            for (int ks = 0; ks < 2; ks++) {
                uint32_t bb[2];
                bb[0] = krow[8 * ks + tg];
                bb[1] = krow[8 * ks + tg + 4];
                mma_f16(s[nt], qa[ks], bb);
            }
        }

        uint32_t pa[2][4];
        #pragma unroll
        for (int nt = 0; nt < 4; nt++) {
            float p0 = fast_exp2(s[nt][0]);
            float p1 = fast_exp2(s[nt][1]);
            float p2 = fast_exp2(s[nt][2]);
            float p3 = fast_exp2(s[nt][3]);
            lsum0 += p0 + p1;
            lsum1 += p2 + p3;
            int kp = nt >> 1;
            int hi = (nt & 1) * 2;
            pa[kp][hi + 0] = pack_h2(p0, p1);
            pa[kp][hi + 1] = pack_h2(p2, p3);
        }

        #pragma unroll
        for (int nd = 0; nd < 4; nd++) {
            const uint32_t* vrow = (const uint32_t*)(Vts + (8 * nd + r) * 520) + kb / 2;
            #pragma unroll
            for (int kp = 0; kp < 2; kp++) {
                uint32_t vb[2];
                vb[0] = vrow[8 * kp + tg];
                vb[1] = vrow[8 * kp + tg + 4];
                mma_f16(o[nd], pa[kp], vb);
            }
        }
    }

    // ---- row sums, normalize, stage O to smem (Osm aliases Ks: barrier first)
    float v0 = lsum0;
    v0 += __shfl_xor_sync(0xFFFFFFFFu, v0, 1);
    v0 += __shfl_xor_sync(0xFFFFFFFFu, v0, 2);
    float v1 = lsum1;
    v1 += __shfl_xor_sync(0xFFFFFFFFu, v1, 1);
    v1 += __shfl_xor_sync(0xFFFFFFFFu, v1, 2);
    const float inv0 = 1.0f / v0;
    const float inv1 = 1.0f / v1;

    __syncthreads();   // everyone done reading Ks before Osm overwrite

    #pragma unroll
    for (int nd = 0; nd < 4; nd++) {
        int col = 8 * nd + 2 * tg;
        *(float2*)(Osm + (lr + r) * 36 + col) =
            make_float2(o[nd][0] * inv0, o[nd][1] * inv0);
        *(float2*)(Osm + (lr + r + 8) * 36 + col) =
            make_float2(o[nd][2] * inv1, o[nd][3] * inv1);
    }
    __syncwarp();      // warp's own 16 rows written by its own lanes only

    // ---- epilogue: 2 threads per token (16 channels each), +bias +LePE conv
    {
        const int n  = tid >> 1;
        const int dh = (tid & 1) << 4;
        const int ts = n >> 8;
        const int hs = (n >> 2) & 63;
        const int ws = n & 3;
        const int l  = ((tb * TSP + ts) * Hc + hs) * Wc + wb * WSP + ws;

        float acc[16];
        {
            const float4* osp = (const float4*)(Osm + n * 36 + dh);
            #pragma unroll
            for (int q = 0; q < 4; q++) {
                float4 t = osp[q];
                acc[4*q+0] = t.x + Bsm[dh + 4*q + 0];
                acc[4*q+1] = t.y + Bsm[dh + 4*q + 1];
                acc[4*q+2] = t.z + Bsm[dh + 4*q + 2];
                acc[4*q+3] = t.w + Bsm[dh + 4*q + 3];
            }
        }

        #pragma unroll
        for (int kt = -1; kt <= 1; kt++) {
            int tt = ts + kt;
            if (tt < 0 || tt >= TSP) continue;
            for (int kh = -1; kh <= 1; kh++) {
                int hh = hs + kh;
                if (hh < 0 || hh >= HSP) continue;
                #pragma unroll
                for (int kw = -1; kw <= 1; kw++) {
                    int wwi = ws + kw;
                    if (wwi < 0 || wwi >= WSP) continue;
                    int nbr = (tt * HSP + hh) * WSP + wwi;
                    int j   = (kt + 1) * 9 + (kh + 1) * 3 + (kw + 1);
                    const float*  wr = Wsm + j * HD + dh;
                    const __half* vp = Vts + dh * 520 + nbr;
                    #pragma unroll
                    for (int d = 0; d < 16; d++)
                        acc[d] += wr[d] * __half2float(vp[d * 520]);
                }
            }
        }

        float* op = out + ((size_t)b * Lc + l) * Cc + cbase + dh;
        #pragma unroll
        for (int q = 0; q < 4; q++)
            *(float4*)(op + 4 * q) =
                make_float4(acc[4*q+0], acc[4*q+1], acc[4*q+2], acc[4*q+3]);
    }
}

extern "C" void kernel_launch(void* const* d_in, const int* in_sizes, int n_in,
                              void* d_out, int out_size)
{
    const float* qkv    = (const float*)d_in[0];
    const float* lepe_w = (const float*)d_in[1];
    const float* lepe_b = (const float*)d_in[2];
    float* out          = (float*)d_out;

    cudaFuncSetAttribute(lepe_attn_hmma,
                         cudaFuncAttributeMaxDynamicSharedMemorySize, SM_TOTAL);
    lepe_attn_hmma<<<Bc * (Tc / TSP) * (Wc / WSP) * 4, 1024, SM_TOTAL>>>(
        qkv, lepe_w, lepe_b, out);
}